// round 3
// baseline (speedup 1.0000x reference)
#include <cuda_runtime.h>
#include <cstdint>

#define LOG2F_ 0.6931471805599453f

// ---------------- scratch (__device__ globals; no allocation allowed) ----------
__device__ float g_h[32768 * 64];     // h per layer           (8 MB)
__device__ float g_z[32768 * 192];    // z_same|z_anti|z_nuc   (25 MB)
__device__ float g_hWt[128 * 64];     // hW[l] transposed
__device__ float g_Gt[192 * 128];     // gW[l] transposed+packed
__device__ float g_gbsum[128];        // sum of gb over 3 channels

// ---------------- init: x[b,i,:] = X[:] -------------------------------------
__global__ void init_kernel(const float* __restrict__ X, float* __restrict__ out) {
    size_t g = (size_t)blockIdx.x * blockDim.x + threadIdx.x;   // 4,194,304 total
    out[g] = X[g & 127];
}

// ---------------- per-layer weight prep -------------------------------------
__global__ void prep_kernel(const float* __restrict__ hW, const float* __restrict__ gW,
                            const float* __restrict__ gb, int l) {
    int g = blockIdx.x * blockDim.x + threadIdx.x;   // grid covers 24576
    if (g < 8192) {                 // hWt[d][k] = hW[l][k][d]
        int d = g >> 6, k = g & 63;
        g_hWt[g] = hW[(l * 64 + k) * 128 + d];
    }
    if (g < 24576) {                // Gt[c*64+k][d] = gW[l][c][d][k]
        int kc = g >> 7, d = g & 127;
        int c = kc >> 6, k = kc & 63;
        g_Gt[g] = gW[((l * 3 + c) * 128 + d) * 64 + k];
    }
    if (g < 128) {
        g_gbsum[g] = gb[(l * 3 + 0) * 128 + g] + gb[(l * 3 + 1) * 128 + g]
                   + gb[(l * 3 + 2) * 128 + g];
    }
}

// ---------------- generic tiled GEMM:  C (+)= A[MxK] @ B[KxN] + bias ---------
// B is row-major [K][N] (pre-transposed weights). BM=64, BN=64, BK=16, 128 thr.
__global__ __launch_bounds__(128) void gemm_kernel(
    const float* __restrict__ A, const float* __restrict__ B,
    const float* __restrict__ bias, float* __restrict__ C,
    int M, int K, int N, int accumulate)
{
    __shared__ __align__(16) float As[16][64];
    __shared__ __align__(16) float Bs[16][64];
    int t = threadIdx.x;
    int mT = blockIdx.x * 64, nT = blockIdx.y * 64;
    int tx = t & 7, ty = t >> 3;          // 8 x 16
    float acc[4][8];
#pragma unroll
    for (int r = 0; r < 4; r++)
#pragma unroll
        for (int c = 0; c < 8; c++) acc[r][c] = 0.f;

    for (int k0 = 0; k0 < K; k0 += 16) {
        {   // load A tile (64m x 16k), store transposed [k][m]
            int row = t >> 1, kq = (t & 1) * 8;
            const float* ap = A + (size_t)(mT + row) * K + k0 + kq;
            float4 a0 = *(const float4*)ap;
            float4 a1 = *(const float4*)(ap + 4);
            As[kq + 0][row] = a0.x; As[kq + 1][row] = a0.y;
            As[kq + 2][row] = a0.z; As[kq + 3][row] = a0.w;
            As[kq + 4][row] = a1.x; As[kq + 5][row] = a1.y;
            As[kq + 6][row] = a1.z; As[kq + 7][row] = a1.w;
        }
        {   // load B tile (16k x 64n)
            int kr = t >> 3, nq = (t & 7) * 8;
            const float* bp = B + (size_t)(k0 + kr) * N + nT + nq;
            *(float4*)&Bs[kr][nq]     = *(const float4*)bp;
            *(float4*)&Bs[kr][nq + 4] = *(const float4*)(bp + 4);
        }
        __syncthreads();
#pragma unroll
        for (int kk = 0; kk < 16; kk++) {
            float4 a  = *(float4*)&As[kk][ty * 4];
            float4 b0 = *(float4*)&Bs[kk][tx * 8];
            float4 b1 = *(float4*)&Bs[kk][tx * 8 + 4];
            float av[4] = {a.x, a.y, a.z, a.w};
            float bv[8] = {b0.x, b0.y, b0.z, b0.w, b1.x, b1.y, b1.z, b1.w};
#pragma unroll
            for (int r = 0; r < 4; r++)
#pragma unroll
                for (int c = 0; c < 8; c++) acc[r][c] += av[r] * bv[c];
        }
        __syncthreads();
    }
#pragma unroll
    for (int r = 0; r < 4; r++) {
        int m = mT + ty * 4 + r;
        float* cp = C + (size_t)m * N + nT + tx * 8;
#pragma unroll
        for (int c = 0; c < 8; c++) {
            float v = acc[r][c] + bias[nT + tx * 8 + c];
            if (accumulate) v += cp[c];
            cp[c] = v;
        }
    }
}

// ---------------- fused message kernel (the big one) -------------------------
// One block per batch element b. 256 threads.
// For each i: load E[32][32], stage1: A[j][h]=ssp(E@W1c^T+b1), stage2 per warp:
// w[j][k]=A[j]@W2c[k]+b2, z += w * h[b,j,k]; channel fixed per warp per i-half
// => W2 row lives in 45 registers, reloaded only at i==0, i==16, nuc-phase.
__global__ __launch_bounds__(256) void msg_kernel(
    const float* __restrict__ Ee, const float* __restrict__ Enuc,
    const float* __restrict__ wW1, const float* __restrict__ wb1,
    const float* __restrict__ wW2, const float* __restrict__ wb2,
    const float* __restrict__ Yp, int l)
{
    __shared__ __align__(16) float W1s[3][48 * 36];   // [c][h*36+f], padded
    __shared__ __align__(16) float b1s[3][48];
    __shared__ __align__(16) float Ys[256];           // Y[m][k]
    __shared__ __align__(16) float hsm[2048];         // h[b][j][k]
    __shared__ __align__(16) float Es[32 * 36];       // E[j][f], pad 36
    __shared__ __align__(16) float Aa[32 * 48];       // A[j][h], pad 48 (v4-readable)
    __shared__ __align__(16) float zbuf[4 * 64];

    const int b = blockIdx.x;
    const int t = threadIdx.x;
    const int w = t >> 5, lane = t & 31;

    // --- load layer weights to smem ---
    for (int idx = t; idx < 3 * 45 * 32; idx += 256) {
        int c = idx / (45 * 32), rem = idx % (45 * 32);
        int hh = rem >> 5, f = rem & 31;
        W1s[c][hh * 36 + f] = wW1[(size_t)(l * 3) * 45 * 32 + idx];
    }
    for (int idx = t; idx < 3 * 45; idx += 256)
        b1s[idx / 45][idx % 45] = wb1[l * 3 * 45 + idx];
    for (int idx = t; idx < 256; idx += 256) Ys[idx] = Yp[idx];
    for (int idx = t; idx < 2048; idx += 256) hsm[idx] = g_h[(size_t)b * 2048 + idx];
    __syncthreads();

    // stage-1 map: 8 threads per j
    const int jmy = t >> 3, hsel = t & 7;
    // stage-2 map: warp -> (jgroup, k-half)
    const int jg = w >> 1, kh = w & 1;
    const int k = kh * 32 + lane;

    float W2r[45];
    float b2r = 0.f;
    int curc = -1;

    // ================= electron edges =================
    for (int i = 0; i < 32; i++) {
        int c2 = ((i < 16) == (jg < 2)) ? 0 : 1;
        if (c2 != curc) {
            curc = c2;
            const float* wp = wW2 + ((size_t)(l * 3 + curc) * 64 + k) * 45;
#pragma unroll
            for (int hh = 0; hh < 45; hh++) W2r[hh] = __ldg(wp + hh);
            b2r = wb2[(l * 3 + curc) * 64 + k];
        }
        {   // load E tile: 1024 floats
            int j = t >> 3, fq = t & 7;
            float4 e4 = *(const float4*)(Ee + (((size_t)(b * 32 + i)) * 32 + j) * 32 + fq * 4);
            float* d = &Es[j * 36 + fq * 4];
            d[0] = e4.x; d[1] = e4.y; d[2] = e4.z; d[3] = e4.w;
        }
        __syncthreads();
        {   // stage1: A[j][h] = ssp(E[j] . W1[c][h] + b1)
            int c = ((i < 16) == (jmy < 16)) ? 0 : 1;
            float acc[6] = {0, 0, 0, 0, 0, 0};
#pragma unroll
            for (int f4 = 0; f4 < 8; f4++) {
                float4 e = *(float4*)&Es[jmy * 36 + f4 * 4];
#pragma unroll
                for (int r = 0; r < 6; r++) {
                    int hh = hsel + 8 * r;
                    float4 ww = *(float4*)&W1s[c][hh * 36 + f4 * 4];
                    acc[r] += e.x * ww.x + e.y * ww.y + e.z * ww.z + e.w * ww.w;
                }
            }
#pragma unroll
            for (int r = 0; r < 6; r++) {
                int hh = hsel + 8 * r;
                if (hh < 45) {
                    float v = acc[r] + b1s[c][hh];
                    Aa[jmy * 48 + hh] = fmaxf(v, 0.f)
                        + __logf(1.f + __expf(-fabsf(v))) - LOG2F_;
                }
            }
        }
        __syncthreads();
        {   // stage2: per warp over its 8 j's
            float zs = 0.f;
            int j0 = jg * 8;
#pragma unroll
            for (int j = j0; j < j0 + 8; j++) {
                if (j == i) continue;
                const float* ap = &Aa[j * 48];
                float wk = b2r;
#pragma unroll
                for (int g = 0; g < 11; g++) {
                    float4 a = *(const float4*)(ap + g * 4);
                    wk += a.x * W2r[4 * g] + a.y * W2r[4 * g + 1]
                        + a.z * W2r[4 * g + 2] + a.w * W2r[4 * g + 3];
                }
                wk += ap[44] * W2r[44];
                zs += wk * hsm[j * 64 + k];
            }
            zbuf[jg * 64 + k] = zs;
        }
        __syncthreads();
        if (t < 128) {   // combine two j-groups per spin class, write z
            int which = t >> 6, kk2 = t & 63;
            int gbse = ((which == 0) == (i < 16)) ? 0 : 2;
            float v = zbuf[gbse * 64 + kk2] + zbuf[(gbse + 1) * 64 + kk2];
            g_z[((size_t)(b * 32 + i) * 3 + which) * 64 + kk2] = v;
        }
        __syncthreads();
    }

    // ================= nuclear edges (channel 2) =================
    {
        const float* wp = wW2 + ((size_t)(l * 3 + 2) * 64 + k) * 45;
#pragma unroll
        for (int hh = 0; hh < 45; hh++) W2r[hh] = __ldg(wp + hh);
        b2r = wb2[(l * 3 + 2) * 64 + k];
    }
    for (int i = 0; i < 32; i++) {
        if (t < 32) {
            int m = t >> 3, fq = t & 7;
            float4 e4 = *(const float4*)(Enuc + (((size_t)(b * 32 + i)) * 4 + m) * 32 + fq * 4);
            float* d = &Es[m * 36 + fq * 4];
            d[0] = e4.x; d[1] = e4.y; d[2] = e4.z; d[3] = e4.w;
        }
        __syncthreads();
        if (t < 32) {   // stage1 for 4 m rows
            float acc[6] = {0, 0, 0, 0, 0, 0};
#pragma unroll
            for (int f4 = 0; f4 < 8; f4++) {
                float4 e = *(float4*)&Es[jmy * 36 + f4 * 4];
#pragma unroll
                for (int r = 0; r < 6; r++) {
                    int hh = hsel + 8 * r;
                    float4 ww = *(float4*)&W1s[2][hh * 36 + f4 * 4];
                    acc[r] += e.x * ww.x + e.y * ww.y + e.z * ww.z + e.w * ww.w;
                }
            }
#pragma unroll
            for (int r = 0; r < 6; r++) {
                int hh = hsel + 8 * r;
                if (hh < 45) {
                    float v = acc[r] + b1s[2][hh];
                    Aa[jmy * 48 + hh] = fmaxf(v, 0.f)
                        + __logf(1.f + __expf(-fabsf(v))) - LOG2F_;
                }
            }
        }
        __syncthreads();
        {   // stage2: warp -> m = jg (0..3)
            const float* ap = &Aa[jg * 48];
            float wk = b2r;
#pragma unroll
            for (int g = 0; g < 11; g++) {
                float4 a = *(const float4*)(ap + g * 4);
                wk += a.x * W2r[4 * g] + a.y * W2r[4 * g + 1]
                    + a.z * W2r[4 * g + 2] + a.w * W2r[4 * g + 3];
            }
            wk += ap[44] * W2r[44];
            zbuf[jg * 64 + k] = wk * Ys[jg * 64 + k];
        }
        __syncthreads();
        if (t < 64) {
            float v = zbuf[t] + zbuf[64 + t] + zbuf[128 + t] + zbuf[192 + t];
            g_z[((size_t)(b * 32 + i) * 3 + 2) * 64 + t] = v;
        }
        __syncthreads();
    }
}

// ---------------- launch -----------------------------------------------------
extern "C" void kernel_launch(void* const* d_in, const int* in_sizes, int n_in,
                              void* d_out, int out_size) {
    const float* Ee  = (const float*)d_in[0];
    const float* En  = (const float*)d_in[1];
    const float* X   = (const float*)d_in[2];
    const float* Y   = (const float*)d_in[3];
    const float* wW1 = (const float*)d_in[4];
    const float* wb1 = (const float*)d_in[5];
    const float* wW2 = (const float*)d_in[6];
    const float* wb2 = (const float*)d_in[7];
    const float* hW  = (const float*)d_in[8];
    const float* hb  = (const float*)d_in[9];
    const float* gW  = (const float*)d_in[10];
    const float* gb  = (const float*)d_in[11];
    float* x = (float*)d_out;   // x lives in d_out the whole time

    float *hbuf, *zbuf, *hWt, *Gt, *gbs;
    cudaGetSymbolAddress((void**)&hbuf, g_h);
    cudaGetSymbolAddress((void**)&zbuf, g_z);
    cudaGetSymbolAddress((void**)&hWt,  g_hWt);
    cudaGetSymbolAddress((void**)&Gt,   g_Gt);
    cudaGetSymbolAddress((void**)&gbs,  g_gbsum);

    init_kernel<<<16384, 256>>>(X, x);
    for (int l = 0; l < 3; l++) {
        prep_kernel<<<96, 256>>>(hW, gW, gb, l);
        // h = x @ hWt + hb[l]   (M=32768, K=128, N=64)
        gemm_kernel<<<dim3(512, 1), 128>>>(x, hWt, hb + l * 64, hbuf,
                                           32768, 128, 64, 0);
        // messages -> g_z
        msg_kernel<<<1024, 256>>>(Ee, En, wW1, wb1, wW2, wb2, Y, l);
        // x += z @ Gt + gbsum   (M=32768, K=192, N=128)
        gemm_kernel<<<dim3(512, 2), 128>>>(zbuf, Gt, gbs, x,
                                           32768, 192, 128, 1);
    }
}

// round 5
// speedup vs baseline: 1.9717x; 1.9717x over previous
#include <cuda_runtime.h>
#include <cstdint>

#define LOG2F_ 0.6931471805599453f

// ---------------- scratch (__device__ globals) --------------------------------
__device__ float g_h[32768 * 64];     // h per layer
__device__ float g_z[32768 * 192];    // z_same|z_anti|z_nuc
__device__ float g_hWt[128 * 64];
__device__ float g_Gt[192 * 128];
__device__ float g_gbsum[128];

// ---------------- helpers -----------------------------------------------------
__device__ __forceinline__ unsigned f2tf(float f) {
    unsigned r;
    asm("cvt.rna.tf32.f32 %0, %1;" : "=r"(r) : "f"(f));
    return r;
}
__device__ __forceinline__ float sspf(float v) {
    return fmaxf(v, 0.f) + __logf(1.f + __expf(-fabsf(v))) - LOG2F_;
}
__device__ __forceinline__ void mma8(float d[4], const unsigned a[4], const unsigned b[2]) {
    asm volatile(
        "mma.sync.aligned.m16n8k8.row.col.f32.tf32.tf32.f32 "
        "{%0,%1,%2,%3}, {%4,%5,%6,%7}, {%8,%9}, {%0,%1,%2,%3};"
        : "+f"(d[0]), "+f"(d[1]), "+f"(d[2]), "+f"(d[3])
        : "r"(a[0]), "r"(a[1]), "r"(a[2]), "r"(a[3]), "r"(b[0]), "r"(b[1]));
}

// ---------------- init --------------------------------------------------------
__global__ void init_kernel(const float* __restrict__ X, float* __restrict__ out) {
    size_t g = (size_t)blockIdx.x * blockDim.x + threadIdx.x;
    out[g] = X[g & 127];
}

// ---------------- per-layer weight prep ---------------------------------------
__global__ void prep_kernel(const float* __restrict__ hW, const float* __restrict__ gW,
                            const float* __restrict__ gb, int l) {
    int g = blockIdx.x * blockDim.x + threadIdx.x;
    if (g < 8192) {
        int d = g >> 6, k = g & 63;
        g_hWt[g] = hW[(l * 64 + k) * 128 + d];
    }
    if (g < 24576) {
        int kc = g >> 7, d = g & 127;
        int c = kc >> 6, k = kc & 63;
        g_Gt[g] = gW[((l * 3 + c) * 128 + d) * 64 + k];
    }
    if (g < 128) {
        g_gbsum[g] = gb[(l * 3 + 0) * 128 + g] + gb[(l * 3 + 1) * 128 + g]
                   + gb[(l * 3 + 2) * 128 + g];
    }
}

// ---------------- generic tiled GEMM ------------------------------------------
__global__ __launch_bounds__(128) void gemm_kernel(
    const float* __restrict__ A, const float* __restrict__ B,
    const float* __restrict__ bias, float* __restrict__ C,
    int M, int K, int N, int accumulate)
{
    __shared__ __align__(16) float As[16][64];
    __shared__ __align__(16) float Bs[16][64];
    int t = threadIdx.x;
    int mT = blockIdx.x * 64, nT = blockIdx.y * 64;
    int tx = t & 7, ty = t >> 3;
    float acc[4][8];
#pragma unroll
    for (int r = 0; r < 4; r++)
#pragma unroll
        for (int c = 0; c < 8; c++) acc[r][c] = 0.f;

    for (int k0 = 0; k0 < K; k0 += 16) {
        {
            int row = t >> 1, kq = (t & 1) * 8;
            const float* ap = A + (size_t)(mT + row) * K + k0 + kq;
            float4 a0 = *(const float4*)ap;
            float4 a1 = *(const float4*)(ap + 4);
            As[kq + 0][row] = a0.x; As[kq + 1][row] = a0.y;
            As[kq + 2][row] = a0.z; As[kq + 3][row] = a0.w;
            As[kq + 4][row] = a1.x; As[kq + 5][row] = a1.y;
            As[kq + 6][row] = a1.z; As[kq + 7][row] = a1.w;
        }
        {
            int kr = t >> 3, nq = (t & 7) * 8;
            const float* bp = B + (size_t)(k0 + kr) * N + nT + nq;
            *(float4*)&Bs[kr][nq]     = *(const float4*)bp;
            *(float4*)&Bs[kr][nq + 4] = *(const float4*)(bp + 4);
        }
        __syncthreads();
#pragma unroll
        for (int kk = 0; kk < 16; kk++) {
            float4 a  = *(float4*)&As[kk][ty * 4];
            float4 b0 = *(float4*)&Bs[kk][tx * 8];
            float4 b1 = *(float4*)&Bs[kk][tx * 8 + 4];
            float av[4] = {a.x, a.y, a.z, a.w};
            float bv[8] = {b0.x, b0.y, b0.z, b0.w, b1.x, b1.y, b1.z, b1.w};
#pragma unroll
            for (int r = 0; r < 4; r++)
#pragma unroll
                for (int c = 0; c < 8; c++) acc[r][c] += av[r] * bv[c];
        }
        __syncthreads();
    }
#pragma unroll
    for (int r = 0; r < 4; r++) {
        int m = mT + ty * 4 + r;
        float* cp = C + (size_t)m * N + nT + tx * 8;
#pragma unroll
        for (int c = 0; c < 8; c++) {
            float v = acc[r][c] + bias[nT + tx * 8 + c];
            if (accumulate) v += cp[c];
            cp[c] = v;
        }
    }
}

// ---------------- tf32 tensor-core message kernel -----------------------------
// Grid 2048: block = (b, i-half). 256 threads, 8 warps.
// Per (b,i):  A = ssp(E @ W1c^T + b1)       [32j x 48h]   (MMA, row i zeroed)
//             G_cls = A_cls^T @ H_cls       [48h x 64k]   (MMA per spin-half)
//             z[k] = sum_h W2c[k,h] G[h,k] + b2c[k]*(Hsum - h[i])  (diag + shfl)
__global__ __launch_bounds__(256) void msg_mma_kernel(
    const float* __restrict__ Ee, const float* __restrict__ Enuc,
    const float* __restrict__ wW1, const float* __restrict__ wb1,
    const float* __restrict__ wW2, const float* __restrict__ wb2,
    const float* __restrict__ Yp, int l)
{
    __shared__ __align__(16) unsigned W1s[3 * 48 * 36];  // tf32 [c][h*36+f]
    __shared__ __align__(16) unsigned Hs[32 * 72];       // tf32 [j][k], stride 72
    __shared__ __align__(16) unsigned Ysm[8 * 72];       // tf32 [m][k], rows 4-7 zero
    __shared__ __align__(16) unsigned Es[32 * 36];       // tf32 [j][f]
    __shared__ __align__(16) unsigned At[48 * 36];       // tf32 [h][j]
    __shared__ __align__(16) float b1s[3 * 48];
    __shared__ __align__(16) float b2s[3 * 64];
    __shared__ __align__(16) float Hsum[128];
    __shared__ __align__(16) float Ysum[64];
    __shared__ __align__(16) float zsm[128];

    const int b = blockIdx.x >> 1;
    const int ihalf = blockIdx.x & 1;
    const int t = threadIdx.x;
    const int w = t >> 5, lane = t & 31;
    const int g = lane >> 2, tg = lane & 3;

    // ---- zero padded regions ----
    for (int idx = t; idx < 3 * 48 * 36; idx += 256) W1s[idx] = 0u;
    for (int idx = t; idx < 8 * 72;      idx += 256) Ysm[idx] = 0u;
    for (int idx = t; idx < 48 * 36;     idx += 256) At[idx]  = 0u;
    for (int idx = t; idx < 3 * 48;      idx += 256) b1s[idx] = 0.f;
    __syncthreads();

    // ---- load weights / h / Y (tf32-rounded) ----
    for (int idx = t; idx < 3 * 45 * 32; idx += 256) {
        int c = idx / 1440, rem = idx % 1440;
        int hh = rem >> 5, f = rem & 31;
        W1s[c * 1728 + hh * 36 + f] = f2tf(wW1[(size_t)l * 3 * 1440 + idx]);
    }
    for (int idx = t; idx < 3 * 45; idx += 256)
        b1s[(idx / 45) * 48 + idx % 45] = wb1[l * 3 * 45 + idx];
    if (t < 192) b2s[t] = wb2[l * 192 + t];
    for (int idx = t; idx < 2048; idx += 256) {
        int j = idx >> 6, k = idx & 63;
        Hs[j * 72 + k] = f2tf(g_h[(size_t)b * 2048 + idx]);
    }
    if (t < 256) {
        int m = t >> 6, k = t & 63;
        Ysm[m * 72 + k] = f2tf(Yp[t]);
    }
    __syncthreads();
    if (t < 128) {
        int cls = t >> 6, k = t & 63;
        float s = 0.f;
        for (int j = 0; j < 16; j++) s += __uint_as_float(Hs[(cls * 16 + j) * 72 + k]);
        Hsum[t] = s;
    }
    if (t < 64) {
        float s = 0.f;
        for (int m = 0; m < 4; m++) s += __uint_as_float(Ysm[m * 72 + t]);
        Ysum[t] = s;
    }
    __syncthreads();

    const int i0 = ihalf * 16;

    // ================= electron edges =================
    for (int ii = 0; ii < 16; ii++) {
        const int i = i0 + ii;
        {   // load E_i [32j x 32f] -> Es (tf32)
            int j = t >> 3, f4 = t & 7;
            float4 e4 = *(const float4*)(Ee + (((size_t)(b * 32 + i)) * 32 + j) * 32 + 4 * f4);
            uint4 u;
            u.x = f2tf(e4.x); u.y = f2tf(e4.y); u.z = f2tf(e4.z); u.w = f2tf(e4.w);
            *(uint4*)&Es[j * 36 + 4 * f4] = u;
        }
        __syncthreads();
        // ---- step1: A = ssp(E @ W1c^T + b1), stored transposed into At ----
        if (w < 6) {
            const int nt = w;
#pragma unroll
            for (int mt = 0; mt < 2; mt++) {
                const int c = ((mt == 0) == (i < 16)) ? 0 : 1;
                float d[4] = {0.f, 0.f, 0.f, 0.f};
#pragma unroll
                for (int kt = 0; kt < 4; kt++) {
                    unsigned a[4], bf[2];
                    int ar = mt * 16 + g, ac = kt * 8 + tg;
                    a[0] = Es[ar * 36 + ac];
                    a[1] = Es[(ar + 8) * 36 + ac];
                    a[2] = Es[ar * 36 + ac + 4];
                    a[3] = Es[(ar + 8) * 36 + ac + 4];
                    int h = nt * 8 + g, f = kt * 8 + tg;
                    bf[0] = W1s[c * 1728 + h * 36 + f];
                    bf[1] = W1s[c * 1728 + h * 36 + f + 4];
                    mma8(d, a, bf);
                }
                int h0 = nt * 8 + 2 * tg, h1 = h0 + 1;
                int j0 = mt * 16 + g, j1 = j0 + 8;
                const float* bb = &b1s[c * 48];
                if (h0 < 45) {
                    At[h0 * 36 + j0] = (j0 == i) ? 0u : f2tf(sspf(d[0] + bb[h0]));
                    At[h0 * 36 + j1] = (j1 == i) ? 0u : f2tf(sspf(d[2] + bb[h0]));
                }
                if (h1 < 45) {
                    At[h1 * 36 + j0] = (j0 == i) ? 0u : f2tf(sspf(d[1] + bb[h1]));
                    At[h1 * 36 + j1] = (j1 == i) ? 0u : f2tf(sspf(d[3] + bb[h1]));
                }
            }
        }
        __syncthreads();
        // ---- step2: G_cls = At_cls @ H_cls ;  step3: diag(W2 G) ----
        {
            const int cls = w & 1, n0 = (w >> 1) * 2;
            float acc[2][3][4];
#pragma unroll
            for (int ntl = 0; ntl < 2; ntl++)
#pragma unroll
                for (int mt = 0; mt < 3; mt++)
#pragma unroll
                    for (int q = 0; q < 4; q++) acc[ntl][mt][q] = 0.f;
#pragma unroll
            for (int ntl = 0; ntl < 2; ntl++) {
#pragma unroll
                for (int mt = 0; mt < 3; mt++) {
#pragma unroll
                    for (int kt = 0; kt < 2; kt++) {
                        unsigned a[4], bf[2];
                        int hr = mt * 16 + g, jc = cls * 16 + kt * 8 + tg;
                        a[0] = At[hr * 36 + jc];
                        a[1] = At[(hr + 8) * 36 + jc];
                        a[2] = At[hr * 36 + jc + 4];
                        a[3] = At[(hr + 8) * 36 + jc + 4];
                        int kcol = (n0 + ntl) * 8 + g;
                        bf[0] = Hs[jc * 72 + kcol];
                        bf[1] = Hs[(jc + 4) * 72 + kcol];
                        mma8(acc[ntl][mt], a, bf);
                    }
                }
            }
            const int c3 = ((cls == 0) == (i < 16)) ? 0 : 1;
#pragma unroll
            for (int ntl = 0; ntl < 2; ntl++) {
#pragma unroll
                for (int par = 0; par < 2; par++) {
                    int k = (n0 + ntl) * 8 + 2 * tg + par;
                    const float* wp = wW2 + ((size_t)(l * 3 + c3) * 64 + k) * 45;
                    float s = 0.f;
#pragma unroll
                    for (int mt = 0; mt < 3; mt++) {
                        int h0 = mt * 16 + g, h1 = h0 + 8;
                        int h1c = h1 < 45 ? h1 : 44;   // acc is 0 for h>=45
                        s += acc[ntl][mt][par]     * __ldg(wp + h0);
                        s += acc[ntl][mt][par + 2] * __ldg(wp + h1c);
                    }
                    s += __shfl_xor_sync(0xffffffffu, s, 4);
                    s += __shfl_xor_sync(0xffffffffu, s, 8);
                    s += __shfl_xor_sync(0xffffffffu, s, 16);
                    if (lane < 4) zsm[cls * 64 + k] = s;
                }
            }
        }
        __syncthreads();
        if (t < 128) {   // writeout z_same / z_anti
            int cw = t >> 6, k = t & 63;
            int ch = ((cw == 0) == (i < 16)) ? 0 : 1;
            int iclass = (i < 16) ? 0 : 1;
            float hs = Hsum[cw * 64 + k]
                     - (cw == iclass ? __uint_as_float(Hs[i * 72 + k]) : 0.f);
            float v = zsm[cw * 64 + k] + b2s[ch * 64 + k] * hs;
            g_z[((size_t)(b * 32 + i) * 3 + ch) * 64 + k] = v;
        }
        __syncthreads();
    }

    // ================= nuclear edges (channel 2) =================
    if (t < 192) {   // zero At columns 4..7 (K-padding for K=4 MMA)
        int h = t >> 2, cc = 4 + (t & 3);
        At[h * 36 + cc] = 0u;
    }
    __syncthreads();
    for (int ii = 0; ii < 16; ii++) {
        const int i = i0 + ii;
        if (t < 32) {
            int m = t >> 3, f4 = t & 7;
            float4 e4 = *(const float4*)(Enuc + (((size_t)(b * 32 + i)) * 4 + m) * 32 + 4 * f4);
            uint4 u;
            u.x = f2tf(e4.x); u.y = f2tf(e4.y); u.z = f2tf(e4.z); u.w = f2tf(e4.w);
            *(uint4*)&Es[m * 36 + 4 * f4] = u;
        }
        __syncthreads();
        if (w < 6) {   // step1 nuc: rows m=0..3 valid
            const int nt = w;
            float d[4] = {0.f, 0.f, 0.f, 0.f};
#pragma unroll
            for (int kt = 0; kt < 4; kt++) {
                unsigned a[4], bf[2];
                int ac = kt * 8 + tg;
                a[0] = Es[g * 36 + ac];
                a[1] = Es[(g + 8) * 36 + ac];
                a[2] = Es[g * 36 + ac + 4];
                a[3] = Es[(g + 8) * 36 + ac + 4];
                int h = nt * 8 + g, f = kt * 8 + tg;
                bf[0] = W1s[2 * 1728 + h * 36 + f];
                bf[1] = W1s[2 * 1728 + h * 36 + f + 4];
                mma8(d, a, bf);
            }
            if (g < 4) {
                int h0 = nt * 8 + 2 * tg, h1 = h0 + 1;
                const float* bb = &b1s[2 * 48];
                if (h0 < 45) At[h0 * 36 + g] = f2tf(sspf(d[0] + bb[h0]));
                if (h1 < 45) At[h1 * 36 + g] = f2tf(sspf(d[1] + bb[h1]));
            }
        }
        __syncthreads();
        {   // step2 nuc: G = At[:, 0:4] @ Y   (K=8 with zero pad); step3
            const int nt = w;
            float acc[3][4];
#pragma unroll
            for (int mt = 0; mt < 3; mt++)
#pragma unroll
                for (int q = 0; q < 4; q++) acc[mt][q] = 0.f;
#pragma unroll
            for (int mt = 0; mt < 3; mt++) {
                unsigned a[4], bf[2];
                int hr = mt * 16 + g;
                a[0] = At[hr * 36 + tg];
                a[1] = At[(hr + 8) * 36 + tg];
                a[2] = At[hr * 36 + tg + 4];
                a[3] = At[(hr + 8) * 36 + tg + 4];
                int kcol = nt * 8 + g;
                bf[0] = Ysm[tg * 72 + kcol];
                bf[1] = Ysm[(tg + 4) * 72 + kcol];
                mma8(acc[mt], a, bf);
            }
#pragma unroll
            for (int par = 0; par < 2; par++) {
                int k = nt * 8 + 2 * tg + par;
                const float* wp = wW2 + ((size_t)(l * 3 + 2) * 64 + k) * 45;
                float s = 0.f;
#pragma unroll
                for (int mt = 0; mt < 3; mt++) {
                    int h0 = mt * 16 + g, h1 = h0 + 8;
                    int h1c = h1 < 45 ? h1 : 44;
                    s += acc[mt][par]     * __ldg(wp + h0);
                    s += acc[mt][par + 2] * __ldg(wp + h1c);
                }
                s += __shfl_xor_sync(0xffffffffu, s, 4);
                s += __shfl_xor_sync(0xffffffffu, s, 8);
                s += __shfl_xor_sync(0xffffffffu, s, 16);
                if (lane < 4) zsm[k] = s;
            }
        }
        __syncthreads();
        if (t < 64) {
            float v = zsm[t] + b2s[128 + t] * Ysum[t];
            g_z[((size_t)(b * 32 + i) * 3 + 2) * 64 + t] = v;
        }
        __syncthreads();
    }
}

// ---------------- launch ------------------------------------------------------
extern "C" void kernel_launch(void* const* d_in, const int* in_sizes, int n_in,
                              void* d_out, int out_size) {
    const float* Ee  = (const float*)d_in[0];
    const float* En  = (const float*)d_in[1];
    const float* X   = (const float*)d_in[2];
    const float* Y   = (const float*)d_in[3];
    const float* wW1 = (const float*)d_in[4];
    const float* wb1 = (const float*)d_in[5];
    const float* wW2 = (const float*)d_in[6];
    const float* wb2 = (const float*)d_in[7];
    const float* hW  = (const float*)d_in[8];
    const float* hb  = (const float*)d_in[9];
    const float* gW  = (const float*)d_in[10];
    const float* gb  = (const float*)d_in[11];
    float* x = (float*)d_out;

    float *hbuf, *zbuf, *hWt, *Gt, *gbs;
    cudaGetSymbolAddress((void**)&hbuf, g_h);
    cudaGetSymbolAddress((void**)&zbuf, g_z);
    cudaGetSymbolAddress((void**)&hWt,  g_hWt);
    cudaGetSymbolAddress((void**)&Gt,   g_Gt);
    cudaGetSymbolAddress((void**)&gbs,  g_gbsum);

    init_kernel<<<16384, 256>>>(X, x);
    for (int l = 0; l < 3; l++) {
        prep_kernel<<<96, 256>>>(hW, gW, gb, l);
        gemm_kernel<<<dim3(512, 1), 128>>>(x, hWt, hb + l * 64, hbuf,
                                           32768, 128, 64, 0);
        msg_mma_kernel<<<2048, 256>>>(Ee, En, wW1, wb1, wW2, wb2, Y, l);
        gemm_kernel<<<dim3(512, 2), 128>>>(zbuf, Gt, gbs, x,
                                           32768, 192, 128, 1);
    }
}